// round 12
// baseline (speedup 1.0000x reference)
#include <cuda_runtime.h>
#include <math.h>

#define NN 100000
#define EE 1200000
#define HIDV 64
#define NHEAD 4
#define NLAYER 3
#define GEMM_GRID 592
#define GEMM_THREADS 256

// ---------------- device scratch (static, no allocations) ----------------
__device__ __align__(16) float g_h[NN * HIDV];   // node features (updated per layer)
__device__ __align__(16) float g_hw[NN * HIDV];  // h @ w_gat[l]
__device__ __align__(16) float g_as[NN * NHEAD]; // attention src terms
__device__ __align__(16) float g_ad[NN * NHEAD]; // attention dst terms
__device__ __align__(16) float g_sc[EE * NHEAD]; // spill buffer for deg>32 nodes
__device__ int   g_src[EE];             // CSR: src node per (dst-sorted) edge
__device__ float g_t[EE];               // CSR: edge scalar attr
__device__ int   g_deg[NN];
__device__ int   g_offs[NN + 1];
__device__ int   g_cur[NN];
__device__ float g_c0[NLAYER * NHEAD];  // edge-term affine coefficients
__device__ float g_c1[NLAYER * NHEAD];

// ---------------- f32x2 packed-math helpers ----------------
__device__ __forceinline__ unsigned long long pack2(float lo, float hi) {
    unsigned long long r;
    asm("mov.b64 %0, {%1, %2};" : "=l"(r) : "f"(lo), "f"(hi));
    return r;
}
__device__ __forceinline__ void unpack2(unsigned long long v, float& lo, float& hi) {
    asm("mov.b64 {%0, %1}, %2;" : "=f"(lo), "=f"(hi) : "l"(v));
}
__device__ __forceinline__ unsigned long long fma2(unsigned long long a,
                                                   unsigned long long b,
                                                   unsigned long long c) {
    unsigned long long d;
    asm("fma.rn.f32x2 %0, %1, %2, %3;" : "=l"(d) : "l"(a), "l"(b), "l"(c));
    return d;
}

// ---------------- CSR build ----------------
__global__ void zero_deg_kernel(int n) {
    int i = blockIdx.x * blockDim.x + threadIdx.x;
    if (i < n) g_deg[i] = 0;
}

// 4 edges per thread (int4 loads) for MLP on the atomics
__global__ void count_deg_kernel(const int* __restrict__ ei, int e) {
    int idx = blockIdx.x * blockDim.x + threadIdx.x;
    int i0 = idx * 4;
    if (i0 + 3 < e) {
        int4 d4 = *(const int4*)(ei + e + i0);
        atomicAdd(&g_deg[d4.x], 1);
        atomicAdd(&g_deg[d4.y], 1);
        atomicAdd(&g_deg[d4.z], 1);
        atomicAdd(&g_deg[d4.w], 1);
    } else {
        for (int i = i0; i < e; i++) atomicAdd(&g_deg[ei[e + i]], 1);
    }
}

// single-block scan over degrees -> offsets (+ copy into cursors)
__global__ void scan_kernel(int n) {
    __shared__ int wsum[32];
    int tid = threadIdx.x;
    int per = (n + 1023) >> 10;
    int start = tid * per;
    int end = min(start + per, n);
    int s = 0;
    for (int i = start; i < end; i++) s += g_deg[i];
    int lane = tid & 31, wid = tid >> 5;
    int v = s;
#pragma unroll
    for (int o = 1; o < 32; o <<= 1) {
        int t = __shfl_up_sync(0xffffffffu, v, o);
        if (lane >= o) v += t;
    }
    if (lane == 31) wsum[wid] = v;
    __syncthreads();
    if (wid == 0) {
        int w = wsum[lane];
#pragma unroll
        for (int o = 1; o < 32; o <<= 1) {
            int t = __shfl_up_sync(0xffffffffu, w, o);
            if (lane >= o) w += t;
        }
        wsum[lane] = w;
    }
    __syncthreads();
    int excl = v - s + (wid > 0 ? wsum[wid - 1] : 0);
    int run = excl;
    for (int i = start; i < end; i++) {
        g_offs[i] = run;
        g_cur[i] = run;
        run += g_deg[i];
    }
    if (end == n) g_offs[n] = run;
}

__global__ void scatter_kernel(const int* __restrict__ ei,
                               const float* __restrict__ ea, int e) {
    int idx = blockIdx.x * blockDim.x + threadIdx.x;
    int i0 = idx * 4;
    if (i0 + 3 < e) {
        int4 s4 = *(const int4*)(ei + i0);
        int4 d4 = *(const int4*)(ei + e + i0);
        float4 t4 = *(const float4*)(ea + i0);
        int p0 = atomicAdd(&g_cur[d4.x], 1);
        int p1 = atomicAdd(&g_cur[d4.y], 1);
        int p2 = atomicAdd(&g_cur[d4.z], 1);
        int p3 = atomicAdd(&g_cur[d4.w], 1);
        g_src[p0] = s4.x; g_t[p0] = t4.x;
        g_src[p1] = s4.y; g_t[p1] = t4.y;
        g_src[p2] = s4.z; g_t[p2] = t4.z;
        g_src[p3] = s4.w; g_t[p3] = t4.w;
    } else {
        for (int i = i0; i < e; i++) {
            int pos = atomicAdd(&g_cur[ei[e + i]], 1);
            g_src[pos] = ei[i];
            g_t[pos] = ea[i];
        }
    }
}

// ---------------- edge-term coefficients: a_e = c0 + c1*t ----------------
__global__ void edge_coef_kernel(const float* __restrict__ w_ee,
                                 const float* __restrict__ b_ee,
                                 const float* __restrict__ w_eg,
                                 const float* __restrict__ att_edge) {
    int j = threadIdx.x;  // 64 threads
    for (int l = 0; l < NLAYER; l++) {
        float u1 = 0.f, u0 = 0.f;
        for (int k = 0; k < HIDV; k++) {
            float w = w_eg[l * HIDV * HIDV + k * HIDV + j];
            u1 = fmaf(w_ee[k], w, u1);
            u0 = fmaf(b_ee[k], w, u0);
        }
        float a = att_edge[l * HIDV + j];
        float v1 = u1 * a, v0 = u0 * a;
#pragma unroll
        for (int o = 8; o > 0; o >>= 1) {
            v1 += __shfl_down_sync(0xffffffffu, v1, o, 16);
            v0 += __shfl_down_sync(0xffffffffu, v0, o, 16);
        }
        if ((j & 15) == 0) {
            g_c1[l * NHEAD + (j >> 4)] = v1;
            g_c0[l * NHEAD + (j >> 4)] = v0;
        }
    }
}

// ---------------- persistent node encoder: h = relu(x@W1+b1)@W2+b2 ----------------
__global__ void __launch_bounds__(GEMM_THREADS)
encoder_kernel(int n, const float* __restrict__ x,
               const float* __restrict__ w1, const float* __restrict__ b1,
               const float* __restrict__ w2, const float* __restrict__ b2) {
    __shared__ float sW1[6 * 64];
    __shared__ float sB1[64];
    __shared__ float sW2[64 * 64];
    __shared__ float sB2[64];
    __shared__ __align__(16) float sX[16][8];       // 16 nodes x 6 inputs (padded)
    __shared__ __align__(16) float4 sH4[4][64];     // relu output, 4-node packs
    int tid = threadIdx.x;
    for (int i = tid; i < 6 * 64; i += GEMM_THREADS) sW1[i] = w1[i];
    for (int i = tid; i < 64 * 64; i += GEMM_THREADS) sW2[i] = w2[i];
    if (tid < 64) { sB1[tid] = b1[tid]; sB2[tid] = b2[tid]; }

    int g = tid >> 6, j = tid & 63;
    int ntiles = (n + 15) >> 4;
    for (int tile = blockIdx.x; tile < ntiles; tile += gridDim.x) {
        int base = tile << 4;
        __syncthreads();
        if (tid < 96) {
            int nl = tid / 6, k = tid % 6;
            int node = base + nl;
            sX[nl][k] = (node < n) ? x[node * 6 + k] : 0.f;
        }
        __syncthreads();
        // phase 1: 16 nodes x 64 hidden, write packed into sH4
        for (int idx = tid; idx < 1024; idx += GEMM_THREADS) {
            int nl = idx >> 6, k = idx & 63;
            float acc = sB1[k];
#pragma unroll
            for (int q = 0; q < 6; q++) acc = fmaf(sX[nl][q], sW1[q * 64 + k], acc);
            ((float*)&sH4[nl >> 2][k])[nl & 3] = fmaxf(acc, 0.f);
        }
        __syncthreads();
        // phase 2: packed-f32x2 GEMM
        unsigned long long acc01 = 0ull, acc23 = 0ull;
#pragma unroll 8
        for (int k = 0; k < 64; k++) {
            float w = sW2[k * 64 + j];
            unsigned long long w2p = pack2(w, w);
            float4 hv = sH4[g][k];
            acc01 = fma2(pack2(hv.x, hv.y), w2p, acc01);
            acc23 = fma2(pack2(hv.z, hv.w), w2p, acc23);
        }
        float a0, a1, a2, a3;
        unpack2(acc01, a0, a1); unpack2(acc23, a2, a3);
        float bb = sB2[j];
        int n0 = base + g * 4;
        if (n0 + 0 < n) g_h[(n0 + 0) * 64 + j] = a0 + bb;
        if (n0 + 1 < n) g_h[(n0 + 1) * 64 + j] = a1 + bb;
        if (n0 + 2 < n) g_h[(n0 + 2) * 64 + j] = a2 + bb;
        if (n0 + 3 < n) g_h[(n0 + 3) * 64 + j] = a3 + bb;
    }
}

// ---------------- persistent per-layer transform: hw = h@W, a_s, a_d ----------------
__global__ void __launch_bounds__(GEMM_THREADS)
transform_kernel(int n, int layer, const float* __restrict__ w_gat,
                 const float* __restrict__ att_src,
                 const float* __restrict__ att_dst) {
    __shared__ float sW[64 * 64];
    __shared__ float sAs[64];
    __shared__ float sAd[64];
    __shared__ __align__(16) float4 sH4[4][64];
    int tid = threadIdx.x;
    const float* W = w_gat + layer * 64 * 64;
    for (int i = tid; i < 64 * 64; i += GEMM_THREADS) sW[i] = W[i];
    if (tid < 64) {
        sAs[tid] = att_src[layer * 64 + tid];
        sAd[tid] = att_dst[layer * 64 + tid];
    }
    int g = tid >> 6, j = tid & 63;
    float asv_ = 0.f, adv_ = 0.f;  // filled after first sync
    int ntiles = (n + 15) >> 4;
    bool first = true;
    for (int tile = blockIdx.x; tile < ntiles; tile += gridDim.x) {
        int base = tile << 4;
        __syncthreads();
        for (int idx = tid; idx < 1024; idx += GEMM_THREADS) {
            int nl = idx >> 6, k = idx & 63;
            int node = base + nl;
            float v = (node < n) ? g_h[node * 64 + k] : 0.f;
            ((float*)&sH4[nl >> 2][k])[nl & 3] = v;
        }
        __syncthreads();
        if (first) { asv_ = sAs[j]; adv_ = sAd[j]; first = false; }
        unsigned long long acc01 = 0ull, acc23 = 0ull;
#pragma unroll 8
        for (int k = 0; k < 64; k++) {
            float w = sW[k * 64 + j];
            unsigned long long w2p = pack2(w, w);
            float4 hv = sH4[g][k];
            acc01 = fma2(pack2(hv.x, hv.y), w2p, acc01);
            acc23 = fma2(pack2(hv.z, hv.w), w2p, acc23);
        }
        float a0, a1, a2, a3;
        unpack2(acc01, a0, a1); unpack2(acc23, a2, a3);
        int n0 = base + g * 4;
        if (n0 + 0 < n) g_hw[(n0 + 0) * 64 + j] = a0;
        if (n0 + 1 < n) g_hw[(n0 + 1) * 64 + j] = a1;
        if (n0 + 2 < n) g_hw[(n0 + 2) * 64 + j] = a2;
        if (n0 + 3 < n) g_hw[(n0 + 3) * 64 + j] = a3;
        float s0 = a0 * asv_, s1 = a1 * asv_, s2 = a2 * asv_, s3 = a3 * asv_;
        float d0 = a0 * adv_, d1 = a1 * adv_, d2 = a2 * adv_, d3 = a3 * adv_;
#pragma unroll
        for (int o = 8; o > 0; o >>= 1) {
            s0 += __shfl_down_sync(0xffffffffu, s0, o, 16);
            s1 += __shfl_down_sync(0xffffffffu, s1, o, 16);
            s2 += __shfl_down_sync(0xffffffffu, s2, o, 16);
            s3 += __shfl_down_sync(0xffffffffu, s3, o, 16);
            d0 += __shfl_down_sync(0xffffffffu, d0, o, 16);
            d1 += __shfl_down_sync(0xffffffffu, d1, o, 16);
            d2 += __shfl_down_sync(0xffffffffu, d2, o, 16);
            d3 += __shfl_down_sync(0xffffffffu, d3, o, 16);
        }
        if ((j & 15) == 0) {
            int h = j >> 4;
            if (n0 + 0 < n) { g_as[(n0 + 0) * 4 + h] = s0; g_ad[(n0 + 0) * 4 + h] = d0; }
            if (n0 + 1 < n) { g_as[(n0 + 1) * 4 + h] = s1; g_ad[(n0 + 1) * 4 + h] = d1; }
            if (n0 + 2 < n) { g_as[(n0 + 2) * 4 + h] = s2; g_ad[(n0 + 2) * 4 + h] = d2; }
            if (n0 + 3 < n) { g_as[(n0 + 3) * 4 + h] = s3; g_ad[(n0 + 3) * 4 + h] = d3; }
        }
    }
}

// ---------------- fused per-layer GAT: softmax + aggregate + ELU + residual + LN
__global__ void gat_fused_kernel(int n, int layer,
                                 const float* __restrict__ b_gat,
                                 const float* __restrict__ ln_g,
                                 const float* __restrict__ ln_b) {
    __shared__ int   sS[4][32];
    __shared__ __align__(16) float sAl[4][128];
    int warp = threadIdx.x >> 5, lane = threadIdx.x & 31;
    int node = blockIdx.x * 4 + warp;
    if (node >= n) return;
    int off = g_offs[node];
    int deg = g_offs[node + 1] - off;

    float4 adv = *(const float4*)&g_ad[node * 4];
    float c00 = g_c0[layer * 4 + 0] + adv.x, c01 = g_c0[layer * 4 + 1] + adv.y;
    float c02 = g_c0[layer * 4 + 2] + adv.z, c03 = g_c0[layer * 4 + 3] + adv.w;
    float c10 = g_c1[layer * 4 + 0], c11 = g_c1[layer * 4 + 1];
    float c12 = g_c1[layer * 4 + 2], c13 = g_c1[layer * 4 + 3];

    int hsel = lane >> 3;  // lane owns dims 2*lane, 2*lane+1 -> head = lane/8
    float ax = 0.f, ay = 0.f;

    if (deg <= 32) {
        // ---- fast path: all scores live in registers, alphas staged in SMEM ----
        int s = 0;
        float sc0 = -1e30f, sc1 = -1e30f, sc2 = -1e30f, sc3 = -1e30f;
        float t = 0.f;
        if (lane < deg) {
            s = g_src[off + lane];
            t = g_t[off + lane];
            float4 av = *(const float4*)&g_as[s * 4];
            sc0 = av.x + c00 + c10 * t;
            sc1 = av.y + c01 + c11 * t;
            sc2 = av.z + c02 + c12 * t;
            sc3 = av.w + c03 + c13 * t;
            sc0 = sc0 > 0.f ? sc0 : 0.2f * sc0;
            sc1 = sc1 > 0.f ? sc1 : 0.2f * sc1;
            sc2 = sc2 > 0.f ? sc2 : 0.2f * sc2;
            sc3 = sc3 > 0.f ? sc3 : 0.2f * sc3;
        }
        float m0 = sc0, m1 = sc1, m2 = sc2, m3 = sc3;
#pragma unroll
        for (int o = 16; o > 0; o >>= 1) {
            m0 = fmaxf(m0, __shfl_xor_sync(0xffffffffu, m0, o));
            m1 = fmaxf(m1, __shfl_xor_sync(0xffffffffu, m1, o));
            m2 = fmaxf(m2, __shfl_xor_sync(0xffffffffu, m2, o));
            m3 = fmaxf(m3, __shfl_xor_sync(0xffffffffu, m3, o));
        }
        float e0 = 0.f, e1 = 0.f, e2 = 0.f, e3 = 0.f;
        if (lane < deg) {
            e0 = __expf(sc0 - m0); e1 = __expf(sc1 - m1);
            e2 = __expf(sc2 - m2); e3 = __expf(sc3 - m3);
        }
        float d0 = e0, d1 = e1, d2 = e2, d3 = e3;
#pragma unroll
        for (int o = 16; o > 0; o >>= 1) {
            d0 += __shfl_xor_sync(0xffffffffu, d0, o);
            d1 += __shfl_xor_sync(0xffffffffu, d1, o);
            d2 += __shfl_xor_sync(0xffffffffu, d2, o);
            d3 += __shfl_xor_sync(0xffffffffu, d3, o);
        }
        float inv0 = 1.f / (d0 + 1e-16f), inv1 = 1.f / (d1 + 1e-16f);
        float inv2 = 1.f / (d2 + 1e-16f), inv3 = 1.f / (d3 + 1e-16f);
        sS[warp][lane] = s;
        float4 ev; ev.x = e0; ev.y = e1; ev.z = e2; ev.w = e3;
        *(float4*)&sAl[warp][lane * 4] = ev;
        __syncwarp();
        float invh = hsel == 0 ? inv0 : (hsel == 1 ? inv1 : (hsel == 2 ? inv2 : inv3));
        for (int i = 0; i < deg; i++) {
            int si = sS[warp][i];
            float alpha = sAl[warp][i * 4 + hsel] * invh;
            float2 v = *(const float2*)&g_hw[si * 64 + 2 * lane];
            ax = fmaf(alpha, v.x, ax);
            ay = fmaf(alpha, v.y, ay);
        }
    } else {
        // ---- generic fallback (rare): 3 passes through g_sc ----
        float m0 = -1e30f, m1 = -1e30f, m2 = -1e30f, m3 = -1e30f;
        for (int basei = 0; basei < deg; basei += 32) {
            int i = basei + lane;
            if (i < deg) {
                int s = g_src[off + i];
                float t = g_t[off + i];
                float4 av = *(const float4*)&g_as[s * 4];
                float sc0 = av.x + c00 + c10 * t;
                float sc1 = av.y + c01 + c11 * t;
                float sc2 = av.z + c02 + c12 * t;
                float sc3 = av.w + c03 + c13 * t;
                sc0 = sc0 > 0.f ? sc0 : 0.2f * sc0;
                sc1 = sc1 > 0.f ? sc1 : 0.2f * sc1;
                sc2 = sc2 > 0.f ? sc2 : 0.2f * sc2;
                sc3 = sc3 > 0.f ? sc3 : 0.2f * sc3;
                m0 = fmaxf(m0, sc0); m1 = fmaxf(m1, sc1);
                m2 = fmaxf(m2, sc2); m3 = fmaxf(m3, sc3);
                float4 o; o.x = sc0; o.y = sc1; o.z = sc2; o.w = sc3;
                *(float4*)&g_sc[(off + i) * 4] = o;
            }
        }
#pragma unroll
        for (int o = 16; o > 0; o >>= 1) {
            m0 = fmaxf(m0, __shfl_xor_sync(0xffffffffu, m0, o));
            m1 = fmaxf(m1, __shfl_xor_sync(0xffffffffu, m1, o));
            m2 = fmaxf(m2, __shfl_xor_sync(0xffffffffu, m2, o));
            m3 = fmaxf(m3, __shfl_xor_sync(0xffffffffu, m3, o));
        }
        float d0 = 0.f, d1 = 0.f, d2 = 0.f, d3 = 0.f;
        for (int basei = 0; basei < deg; basei += 32) {
            int i = basei + lane;
            if (i < deg) {
                float4 sv = *(const float4*)&g_sc[(off + i) * 4];
                sv.x = __expf(sv.x - m0); sv.y = __expf(sv.y - m1);
                sv.z = __expf(sv.z - m2); sv.w = __expf(sv.w - m3);
                *(float4*)&g_sc[(off + i) * 4] = sv;
                d0 += sv.x; d1 += sv.y; d2 += sv.z; d3 += sv.w;
            }
        }
#pragma unroll
        for (int o = 16; o > 0; o >>= 1) {
            d0 += __shfl_xor_sync(0xffffffffu, d0, o);
            d1 += __shfl_xor_sync(0xffffffffu, d1, o);
            d2 += __shfl_xor_sync(0xffffffffu, d2, o);
            d3 += __shfl_xor_sync(0xffffffffu, d3, o);
        }
        float inv0 = 1.f / (d0 + 1e-16f), inv1 = 1.f / (d1 + 1e-16f);
        float inv2 = 1.f / (d2 + 1e-16f), inv3 = 1.f / (d3 + 1e-16f);
        float invh = hsel == 0 ? inv0 : (hsel == 1 ? inv1 : (hsel == 2 ? inv2 : inv3));
        for (int i = 0; i < deg; i++) {
            int si = g_src[off + i];
            float alpha = g_sc[(off + i) * 4 + hsel] * invh;
            float2 v = *(const float2*)&g_hw[si * 64 + 2 * lane];
            ax = fmaf(alpha, v.x, ax);
            ay = fmaf(alpha, v.y, ay);
        }
    }

    // epilogue: + b_gat, ELU, residual, LayerNorm (warp-wide over 64 dims)
    float2 bg = *(const float2*)&b_gat[layer * 64 + 2 * lane];
    ax += bg.x; ay += bg.y;
    ax = ax > 0.f ? ax : (__expf(ax) - 1.f);
    ay = ay > 0.f ? ay : (__expf(ay) - 1.f);
    float2 hv = *(const float2*)&g_h[node * 64 + 2 * lane];
    float vx = hv.x + ax, vy = hv.y + ay;
    float s1 = vx + vy;
#pragma unroll
    for (int o = 16; o > 0; o >>= 1) s1 += __shfl_xor_sync(0xffffffffu, s1, o);
    float mean = s1 * (1.f / 64.f);
    float dx = vx - mean, dy = vy - mean;
    float s2 = dx * dx + dy * dy;
#pragma unroll
    for (int o = 16; o > 0; o >>= 1) s2 += __shfl_xor_sync(0xffffffffu, s2, o);
    float r = rsqrtf(s2 * (1.f / 64.f) + 1e-5f);
    float2 gg = *(const float2*)&ln_g[layer * 64 + 2 * lane];
    float2 bb = *(const float2*)&ln_b[layer * 64 + 2 * lane];
    float2 outv;
    outv.x = fmaf(dx * r, gg.x, bb.x);
    outv.y = fmaf(dy * r, gg.y, bb.y);
    *(float2*)&g_h[node * 64 + 2 * lane] = outv;
}

// ---------------- persistent output projection ----------------
__global__ void __launch_bounds__(GEMM_THREADS)
out_kernel(int n, const float* __restrict__ w,
           const float* __restrict__ b, float* __restrict__ out) {
    __shared__ float sW[64 * 64];
    __shared__ float sB[64];
    __shared__ __align__(16) float4 sH4[4][64];
    int tid = threadIdx.x;
    for (int i = tid; i < 64 * 64; i += GEMM_THREADS) sW[i] = w[i];
    if (tid < 64) sB[tid] = b[tid];
    int g = tid >> 6, j = tid & 63;
    int ntiles = (n + 15) >> 4;
    for (int tile = blockIdx.x; tile < ntiles; tile += gridDim.x) {
        int base = tile << 4;
        __syncthreads();
        for (int idx = tid; idx < 1024; idx += GEMM_THREADS) {
            int nl = idx >> 6, k = idx & 63;
            int node = base + nl;
            float v = (node < n) ? g_h[node * 64 + k] : 0.f;
            ((float*)&sH4[nl >> 2][k])[nl & 3] = v;
        }
        __syncthreads();
        unsigned long long acc01 = 0ull, acc23 = 0ull;
#pragma unroll 8
        for (int k = 0; k < 64; k++) {
            float wv = sW[k * 64 + j];
            unsigned long long w2p = pack2(wv, wv);
            float4 hv = sH4[g][k];
            acc01 = fma2(pack2(hv.x, hv.y), w2p, acc01);
            acc23 = fma2(pack2(hv.z, hv.w), w2p, acc23);
        }
        float a0, a1, a2, a3;
        unpack2(acc01, a0, a1); unpack2(acc23, a2, a3);
        float bb = sB[j];
        int n0 = base + g * 4;
        if (n0 + 0 < n) out[(n0 + 0) * 64 + j] = a0 + bb;
        if (n0 + 1 < n) out[(n0 + 1) * 64 + j] = a1 + bb;
        if (n0 + 2 < n) out[(n0 + 2) * 64 + j] = a2 + bb;
        if (n0 + 3 < n) out[(n0 + 3) * 64 + j] = a3 + bb;
    }
}

// ---------------- launcher ----------------
extern "C" void kernel_launch(void* const* d_in, const int* in_sizes, int n_in,
                              void* d_out, int out_size) {
    const float* x       = (const float*)d_in[0];
    const int* ei        = (const int*)d_in[1];     // int64 in reference -> int32 in harness
    const float* ea      = (const float*)d_in[2];
    const float* w_ne1   = (const float*)d_in[3];
    const float* b_ne1   = (const float*)d_in[4];
    const float* w_ne2   = (const float*)d_in[5];
    const float* b_ne2   = (const float*)d_in[6];
    const float* w_ee    = (const float*)d_in[7];
    const float* b_ee    = (const float*)d_in[8];
    const float* w_gat   = (const float*)d_in[9];
    const float* w_eg    = (const float*)d_in[10];
    const float* att_src = (const float*)d_in[11];
    const float* att_dst = (const float*)d_in[12];
    const float* att_edge= (const float*)d_in[13];
    const float* b_gat   = (const float*)d_in[14];
    const float* ln_g    = (const float*)d_in[15];
    const float* ln_b    = (const float*)d_in[16];
    const float* w_out   = (const float*)d_in[17];
    const float* b_out   = (const float*)d_in[18];

    int n = in_sizes[0] / 6;       // nodes
    int e = in_sizes[1] / 2;       // edges

    // CSR build (per call; graph-capturable, deterministic output)
    zero_deg_kernel<<<(n + 255) / 256, 256>>>(n);
    count_deg_kernel<<<(e / 4 + 255) / 256, 256>>>(ei, e);
    scan_kernel<<<1, 1024>>>(n);
    scatter_kernel<<<(e / 4 + 255) / 256, 256>>>(ei, ea, e);

    edge_coef_kernel<<<1, 64>>>(w_ee, b_ee, w_eg, att_edge);
    encoder_kernel<<<GEMM_GRID, GEMM_THREADS>>>(n, x, w_ne1, b_ne1, w_ne2, b_ne2);

    for (int l = 0; l < NLAYER; l++) {
        transform_kernel<<<GEMM_GRID, GEMM_THREADS>>>(n, l, w_gat, att_src, att_dst);
        gat_fused_kernel<<<(n + 3) / 4, 128>>>(n, l, b_gat, ln_g, ln_b);
    }

    out_kernel<<<GEMM_GRID, GEMM_THREADS>>>(n, w_out, b_out, (float*)d_out);
}

// round 13
// speedup vs baseline: 1.0026x; 1.0026x over previous
#include <cuda_runtime.h>
#include <math.h>

#define NN 100000
#define EE 1200000
#define HIDV 64
#define NHEAD 4
#define NLAYER 3
#define GEMM_GRID 592
#define GEMM_THREADS 256

// ---------------- device scratch (static, no allocations) ----------------
__device__ __align__(16) float g_h[NN * HIDV];   // node features (updated per layer)
__device__ __align__(16) float g_hw[NN * HIDV];  // h @ w_gat[l]
__device__ __align__(16) float g_as[NN * NHEAD]; // attention src terms
__device__ __align__(16) float g_ad[NN * NHEAD]; // attention dst terms
__device__ __align__(16) float g_sc[EE * NHEAD]; // spill buffer for deg>32 nodes
__device__ int   g_src[EE];             // CSR: src node per (dst-sorted) edge
__device__ float g_t[EE];               // CSR: edge scalar attr
__device__ int   g_deg[NN];
__device__ int   g_offs[NN + 1];
__device__ int   g_cur[NN];
__device__ float g_c0[NLAYER * NHEAD];  // edge-term affine coefficients
__device__ float g_c1[NLAYER * NHEAD];

// ---------------- f32x2 packed-math helpers ----------------
__device__ __forceinline__ unsigned long long pack2(float lo, float hi) {
    unsigned long long r;
    asm("mov.b64 %0, {%1, %2};" : "=l"(r) : "f"(lo), "f"(hi));
    return r;
}
__device__ __forceinline__ void unpack2(unsigned long long v, float& lo, float& hi) {
    asm("mov.b64 {%0, %1}, %2;" : "=f"(lo), "=f"(hi) : "l"(v));
}
__device__ __forceinline__ unsigned long long fma2(unsigned long long a,
                                                   unsigned long long b,
                                                   unsigned long long c) {
    unsigned long long d;
    asm("fma.rn.f32x2 %0, %1, %2, %3;" : "=l"(d) : "l"(a), "l"(b), "l"(c));
    return d;
}

// ---------------- CSR build ----------------
__global__ void zero_deg_kernel(int n) {
    int i = blockIdx.x * blockDim.x + threadIdx.x;
    if (i < n) g_deg[i] = 0;
}

// 4 edges per thread (int4 loads) for MLP on the atomics
__global__ void count_deg_kernel(const int* __restrict__ ei, int e) {
    int idx = blockIdx.x * blockDim.x + threadIdx.x;
    int i0 = idx * 4;
    if (i0 + 3 < e) {
        int4 d4 = *(const int4*)(ei + e + i0);
        atomicAdd(&g_deg[d4.x], 1);
        atomicAdd(&g_deg[d4.y], 1);
        atomicAdd(&g_deg[d4.z], 1);
        atomicAdd(&g_deg[d4.w], 1);
    } else {
        for (int i = i0; i < e; i++) atomicAdd(&g_deg[ei[e + i]], 1);
    }
}

// single-block scan over degrees -> offsets (+ copy into cursors)
__global__ void scan_kernel(int n) {
    __shared__ int wsum[32];
    int tid = threadIdx.x;
    int per = (n + 1023) >> 10;
    int start = tid * per;
    int end = min(start + per, n);
    int s = 0;
    for (int i = start; i < end; i++) s += g_deg[i];
    int lane = tid & 31, wid = tid >> 5;
    int v = s;
#pragma unroll
    for (int o = 1; o < 32; o <<= 1) {
        int t = __shfl_up_sync(0xffffffffu, v, o);
        if (lane >= o) v += t;
    }
    if (lane == 31) wsum[wid] = v;
    __syncthreads();
    if (wid == 0) {
        int w = wsum[lane];
#pragma unroll
        for (int o = 1; o < 32; o <<= 1) {
            int t = __shfl_up_sync(0xffffffffu, w, o);
            if (lane >= o) w += t;
        }
        wsum[lane] = w;
    }
    __syncthreads();
    int excl = v - s + (wid > 0 ? wsum[wid - 1] : 0);
    int run = excl;
    for (int i = start; i < end; i++) {
        g_offs[i] = run;
        g_cur[i] = run;
        run += g_deg[i];
    }
    if (end == n) g_offs[n] = run;
}

__global__ void scatter_kernel(const int* __restrict__ ei,
                               const float* __restrict__ ea, int e) {
    int idx = blockIdx.x * blockDim.x + threadIdx.x;
    int i0 = idx * 4;
    if (i0 + 3 < e) {
        int4 s4 = *(const int4*)(ei + i0);
        int4 d4 = *(const int4*)(ei + e + i0);
        float4 t4 = *(const float4*)(ea + i0);
        int p0 = atomicAdd(&g_cur[d4.x], 1);
        int p1 = atomicAdd(&g_cur[d4.y], 1);
        int p2 = atomicAdd(&g_cur[d4.z], 1);
        int p3 = atomicAdd(&g_cur[d4.w], 1);
        g_src[p0] = s4.x; g_t[p0] = t4.x;
        g_src[p1] = s4.y; g_t[p1] = t4.y;
        g_src[p2] = s4.z; g_t[p2] = t4.z;
        g_src[p3] = s4.w; g_t[p3] = t4.w;
    } else {
        for (int i = i0; i < e; i++) {
            int pos = atomicAdd(&g_cur[ei[e + i]], 1);
            g_src[pos] = ei[i];
            g_t[pos] = ea[i];
        }
    }
}

// ---------------- edge-term coefficients: a_e = c0 + c1*t ----------------
__global__ void edge_coef_kernel(const float* __restrict__ w_ee,
                                 const float* __restrict__ b_ee,
                                 const float* __restrict__ w_eg,
                                 const float* __restrict__ att_edge) {
    int j = threadIdx.x;  // 64 threads
    for (int l = 0; l < NLAYER; l++) {
        float u1 = 0.f, u0 = 0.f;
        for (int k = 0; k < HIDV; k++) {
            float w = w_eg[l * HIDV * HIDV + k * HIDV + j];
            u1 = fmaf(w_ee[k], w, u1);
            u0 = fmaf(b_ee[k], w, u0);
        }
        float a = att_edge[l * HIDV + j];
        float v1 = u1 * a, v0 = u0 * a;
#pragma unroll
        for (int o = 8; o > 0; o >>= 1) {
            v1 += __shfl_down_sync(0xffffffffu, v1, o, 16);
            v0 += __shfl_down_sync(0xffffffffu, v0, o, 16);
        }
        if ((j & 15) == 0) {
            g_c1[l * NHEAD + (j >> 4)] = v1;
            g_c0[l * NHEAD + (j >> 4)] = v0;
        }
    }
}

// ---------------- persistent node encoder: h = relu(x@W1+b1)@W2+b2 ----------------
__global__ void __launch_bounds__(GEMM_THREADS)
encoder_kernel(int n, const float* __restrict__ x,
               const float* __restrict__ w1, const float* __restrict__ b1,
               const float* __restrict__ w2, const float* __restrict__ b2) {
    __shared__ float sW1[6 * 64];
    __shared__ float sB1[64];
    __shared__ float sW2[64 * 64];
    __shared__ float sB2[64];
    __shared__ __align__(16) float sX[16][8];       // 16 nodes x 6 inputs (padded)
    __shared__ __align__(16) float4 sH4[4][64];     // relu output, 4-node packs
    int tid = threadIdx.x;
    for (int i = tid; i < 6 * 64; i += GEMM_THREADS) sW1[i] = w1[i];
    for (int i = tid; i < 64 * 64; i += GEMM_THREADS) sW2[i] = w2[i];
    if (tid < 64) { sB1[tid] = b1[tid]; sB2[tid] = b2[tid]; }

    int g = tid >> 6, j = tid & 63;
    int ntiles = (n + 15) >> 4;
    for (int tile = blockIdx.x; tile < ntiles; tile += gridDim.x) {
        int base = tile << 4;
        __syncthreads();
        if (tid < 96) {
            int nl = tid / 6, k = tid % 6;
            int node = base + nl;
            sX[nl][k] = (node < n) ? x[node * 6 + k] : 0.f;
        }
        __syncthreads();
        // phase 1: 16 nodes x 64 hidden, write packed into sH4
        for (int idx = tid; idx < 1024; idx += GEMM_THREADS) {
            int nl = idx >> 6, k = idx & 63;
            float acc = sB1[k];
#pragma unroll
            for (int q = 0; q < 6; q++) acc = fmaf(sX[nl][q], sW1[q * 64 + k], acc);
            ((float*)&sH4[nl >> 2][k])[nl & 3] = fmaxf(acc, 0.f);
        }
        __syncthreads();
        // phase 2: packed-f32x2 GEMM
        unsigned long long acc01 = 0ull, acc23 = 0ull;
#pragma unroll 8
        for (int k = 0; k < 64; k++) {
            float w = sW2[k * 64 + j];
            unsigned long long w2p = pack2(w, w);
            float4 hv = sH4[g][k];
            acc01 = fma2(pack2(hv.x, hv.y), w2p, acc01);
            acc23 = fma2(pack2(hv.z, hv.w), w2p, acc23);
        }
        float a0, a1, a2, a3;
        unpack2(acc01, a0, a1); unpack2(acc23, a2, a3);
        float bb = sB2[j];
        int n0 = base + g * 4;
        if (n0 + 0 < n) g_h[(n0 + 0) * 64 + j] = a0 + bb;
        if (n0 + 1 < n) g_h[(n0 + 1) * 64 + j] = a1 + bb;
        if (n0 + 2 < n) g_h[(n0 + 2) * 64 + j] = a2 + bb;
        if (n0 + 3 < n) g_h[(n0 + 3) * 64 + j] = a3 + bb;
    }
}

// ---------------- persistent per-layer transform: hw = h@W, a_s, a_d ----------------
__global__ void __launch_bounds__(GEMM_THREADS)
transform_kernel(int n, int layer, const float* __restrict__ w_gat,
                 const float* __restrict__ att_src,
                 const float* __restrict__ att_dst) {
    __shared__ float sW[64 * 64];
    __shared__ float sAs[64];
    __shared__ float sAd[64];
    __shared__ __align__(16) float4 sH4[4][64];
    int tid = threadIdx.x;
    const float* W = w_gat + layer * 64 * 64;
    for (int i = tid; i < 64 * 64; i += GEMM_THREADS) sW[i] = W[i];
    if (tid < 64) {
        sAs[tid] = att_src[layer * 64 + tid];
        sAd[tid] = att_dst[layer * 64 + tid];
    }
    int g = tid >> 6, j = tid & 63;
    float asv_ = 0.f, adv_ = 0.f;  // filled after first sync
    int ntiles = (n + 15) >> 4;
    bool first = true;
    for (int tile = blockIdx.x; tile < ntiles; tile += gridDim.x) {
        int base = tile << 4;
        __syncthreads();
        for (int idx = tid; idx < 1024; idx += GEMM_THREADS) {
            int nl = idx >> 6, k = idx & 63;
            int node = base + nl;
            float v = (node < n) ? g_h[node * 64 + k] : 0.f;
            ((float*)&sH4[nl >> 2][k])[nl & 3] = v;
        }
        __syncthreads();
        if (first) { asv_ = sAs[j]; adv_ = sAd[j]; first = false; }
        unsigned long long acc01 = 0ull, acc23 = 0ull;
#pragma unroll 8
        for (int k = 0; k < 64; k++) {
            float w = sW[k * 64 + j];
            unsigned long long w2p = pack2(w, w);
            float4 hv = sH4[g][k];
            acc01 = fma2(pack2(hv.x, hv.y), w2p, acc01);
            acc23 = fma2(pack2(hv.z, hv.w), w2p, acc23);
        }
        float a0, a1, a2, a3;
        unpack2(acc01, a0, a1); unpack2(acc23, a2, a3);
        int n0 = base + g * 4;
        if (n0 + 0 < n) g_hw[(n0 + 0) * 64 + j] = a0;
        if (n0 + 1 < n) g_hw[(n0 + 1) * 64 + j] = a1;
        if (n0 + 2 < n) g_hw[(n0 + 2) * 64 + j] = a2;
        if (n0 + 3 < n) g_hw[(n0 + 3) * 64 + j] = a3;
        float s0 = a0 * asv_, s1 = a1 * asv_, s2 = a2 * asv_, s3 = a3 * asv_;
        float d0 = a0 * adv_, d1 = a1 * adv_, d2 = a2 * adv_, d3 = a3 * adv_;
#pragma unroll
        for (int o = 8; o > 0; o >>= 1) {
            s0 += __shfl_down_sync(0xffffffffu, s0, o, 16);
            s1 += __shfl_down_sync(0xffffffffu, s1, o, 16);
            s2 += __shfl_down_sync(0xffffffffu, s2, o, 16);
            s3 += __shfl_down_sync(0xffffffffu, s3, o, 16);
            d0 += __shfl_down_sync(0xffffffffu, d0, o, 16);
            d1 += __shfl_down_sync(0xffffffffu, d1, o, 16);
            d2 += __shfl_down_sync(0xffffffffu, d2, o, 16);
            d3 += __shfl_down_sync(0xffffffffu, d3, o, 16);
        }
        if ((j & 15) == 0) {
            int h = j >> 4;
            if (n0 + 0 < n) { g_as[(n0 + 0) * 4 + h] = s0; g_ad[(n0 + 0) * 4 + h] = d0; }
            if (n0 + 1 < n) { g_as[(n0 + 1) * 4 + h] = s1; g_ad[(n0 + 1) * 4 + h] = d1; }
            if (n0 + 2 < n) { g_as[(n0 + 2) * 4 + h] = s2; g_ad[(n0 + 2) * 4 + h] = d2; }
            if (n0 + 3 < n) { g_as[(n0 + 3) * 4 + h] = s3; g_ad[(n0 + 3) * 4 + h] = d3; }
        }
    }
}

// ---------------- fused per-layer GAT: softmax + aggregate + ELU + residual + LN
__global__ void gat_fused_kernel(int n, int layer,
                                 const float* __restrict__ b_gat,
                                 const float* __restrict__ ln_g,
                                 const float* __restrict__ ln_b) {
    __shared__ int   sS[4][32];
    __shared__ __align__(16) float sAl[4][128];
    int warp = threadIdx.x >> 5, lane = threadIdx.x & 31;
    int node = blockIdx.x * 4 + warp;
    if (node >= n) return;
    int off = g_offs[node];
    int deg = g_offs[node + 1] - off;

    float4 adv = *(const float4*)&g_ad[node * 4];
    float c00 = g_c0[layer * 4 + 0] + adv.x, c01 = g_c0[layer * 4 + 1] + adv.y;
    float c02 = g_c0[layer * 4 + 2] + adv.z, c03 = g_c0[layer * 4 + 3] + adv.w;
    float c10 = g_c1[layer * 4 + 0], c11 = g_c1[layer * 4 + 1];
    float c12 = g_c1[layer * 4 + 2], c13 = g_c1[layer * 4 + 3];

    int hsel = lane >> 3;  // lane owns dims 2*lane, 2*lane+1 -> head = lane/8
    float ax = 0.f, ay = 0.f;

    if (deg <= 32) {
        // ---- fast path: all scores live in registers, alphas staged in SMEM ----
        int s = 0;
        float sc0 = -1e30f, sc1 = -1e30f, sc2 = -1e30f, sc3 = -1e30f;
        float t = 0.f;
        if (lane < deg) {
            s = g_src[off + lane];
            t = g_t[off + lane];
            float4 av = *(const float4*)&g_as[s * 4];
            sc0 = av.x + c00 + c10 * t;
            sc1 = av.y + c01 + c11 * t;
            sc2 = av.z + c02 + c12 * t;
            sc3 = av.w + c03 + c13 * t;
            sc0 = sc0 > 0.f ? sc0 : 0.2f * sc0;
            sc1 = sc1 > 0.f ? sc1 : 0.2f * sc1;
            sc2 = sc2 > 0.f ? sc2 : 0.2f * sc2;
            sc3 = sc3 > 0.f ? sc3 : 0.2f * sc3;
        }
        float m0 = sc0, m1 = sc1, m2 = sc2, m3 = sc3;
#pragma unroll
        for (int o = 16; o > 0; o >>= 1) {
            m0 = fmaxf(m0, __shfl_xor_sync(0xffffffffu, m0, o));
            m1 = fmaxf(m1, __shfl_xor_sync(0xffffffffu, m1, o));
            m2 = fmaxf(m2, __shfl_xor_sync(0xffffffffu, m2, o));
            m3 = fmaxf(m3, __shfl_xor_sync(0xffffffffu, m3, o));
        }
        float e0 = 0.f, e1 = 0.f, e2 = 0.f, e3 = 0.f;
        if (lane < deg) {
            e0 = __expf(sc0 - m0); e1 = __expf(sc1 - m1);
            e2 = __expf(sc2 - m2); e3 = __expf(sc3 - m3);
        }
        float d0 = e0, d1 = e1, d2 = e2, d3 = e3;
#pragma unroll
        for (int o = 16; o > 0; o >>= 1) {
            d0 += __shfl_xor_sync(0xffffffffu, d0, o);
            d1 += __shfl_xor_sync(0xffffffffu, d1, o);
            d2 += __shfl_xor_sync(0xffffffffu, d2, o);
            d3 += __shfl_xor_sync(0xffffffffu, d3, o);
        }
        float inv0 = 1.f / (d0 + 1e-16f), inv1 = 1.f / (d1 + 1e-16f);
        float inv2 = 1.f / (d2 + 1e-16f), inv3 = 1.f / (d3 + 1e-16f);
        sS[warp][lane] = s;
        float4 ev; ev.x = e0; ev.y = e1; ev.z = e2; ev.w = e3;
        *(float4*)&sAl[warp][lane * 4] = ev;
        __syncwarp();
        float invh = hsel == 0 ? inv0 : (hsel == 1 ? inv1 : (hsel == 2 ? inv2 : inv3));
        for (int i = 0; i < deg; i++) {
            int si = sS[warp][i];
            float alpha = sAl[warp][i * 4 + hsel] * invh;
            float2 v = *(const float2*)&g_hw[si * 64 + 2 * lane];
            ax = fmaf(alpha, v.x, ax);
            ay = fmaf(alpha, v.y, ay);
        }
    } else {
        // ---- generic fallback (rare): 3 passes through g_sc ----
        float m0 = -1e30f, m1 = -1e30f, m2 = -1e30f, m3 = -1e30f;
        for (int basei = 0; basei < deg; basei += 32) {
            int i = basei + lane;
            if (i < deg) {
                int s = g_src[off + i];
                float t = g_t[off + i];
                float4 av = *(const float4*)&g_as[s * 4];
                float sc0 = av.x + c00 + c10 * t;
                float sc1 = av.y + c01 + c11 * t;
                float sc2 = av.z + c02 + c12 * t;
                float sc3 = av.w + c03 + c13 * t;
                sc0 = sc0 > 0.f ? sc0 : 0.2f * sc0;
                sc1 = sc1 > 0.f ? sc1 : 0.2f * sc1;
                sc2 = sc2 > 0.f ? sc2 : 0.2f * sc2;
                sc3 = sc3 > 0.f ? sc3 : 0.2f * sc3;
                m0 = fmaxf(m0, sc0); m1 = fmaxf(m1, sc1);
                m2 = fmaxf(m2, sc2); m3 = fmaxf(m3, sc3);
                float4 o; o.x = sc0; o.y = sc1; o.z = sc2; o.w = sc3;
                *(float4*)&g_sc[(off + i) * 4] = o;
            }
        }
#pragma unroll
        for (int o = 16; o > 0; o >>= 1) {
            m0 = fmaxf(m0, __shfl_xor_sync(0xffffffffu, m0, o));
            m1 = fmaxf(m1, __shfl_xor_sync(0xffffffffu, m1, o));
            m2 = fmaxf(m2, __shfl_xor_sync(0xffffffffu, m2, o));
            m3 = fmaxf(m3, __shfl_xor_sync(0xffffffffu, m3, o));
        }
        float d0 = 0.f, d1 = 0.f, d2 = 0.f, d3 = 0.f;
        for (int basei = 0; basei < deg; basei += 32) {
            int i = basei + lane;
            if (i < deg) {
                float4 sv = *(const float4*)&g_sc[(off + i) * 4];
                sv.x = __expf(sv.x - m0); sv.y = __expf(sv.y - m1);
                sv.z = __expf(sv.z - m2); sv.w = __expf(sv.w - m3);
                *(float4*)&g_sc[(off + i) * 4] = sv;
                d0 += sv.x; d1 += sv.y; d2 += sv.z; d3 += sv.w;
            }
        }
#pragma unroll
        for (int o = 16; o > 0; o >>= 1) {
            d0 += __shfl_xor_sync(0xffffffffu, d0, o);
            d1 += __shfl_xor_sync(0xffffffffu, d1, o);
            d2 += __shfl_xor_sync(0xffffffffu, d2, o);
            d3 += __shfl_xor_sync(0xffffffffu, d3, o);
        }
        float inv0 = 1.f / (d0 + 1e-16f), inv1 = 1.f / (d1 + 1e-16f);
        float inv2 = 1.f / (d2 + 1e-16f), inv3 = 1.f / (d3 + 1e-16f);
        float invh = hsel == 0 ? inv0 : (hsel == 1 ? inv1 : (hsel == 2 ? inv2 : inv3));
        for (int i = 0; i < deg; i++) {
            int si = g_src[off + i];
            float alpha = g_sc[(off + i) * 4 + hsel] * invh;
            float2 v = *(const float2*)&g_hw[si * 64 + 2 * lane];
            ax = fmaf(alpha, v.x, ax);
            ay = fmaf(alpha, v.y, ay);
        }
    }

    // epilogue: + b_gat, ELU, residual, LayerNorm (warp-wide over 64 dims)
    float2 bg = *(const float2*)&b_gat[layer * 64 + 2 * lane];
    ax += bg.x; ay += bg.y;
    ax = ax > 0.f ? ax : (__expf(ax) - 1.f);
    ay = ay > 0.f ? ay : (__expf(ay) - 1.f);
    float2 hv = *(const float2*)&g_h[node * 64 + 2 * lane];
    float vx = hv.x + ax, vy = hv.y + ay;
    float s1 = vx + vy;
#pragma unroll
    for (int o = 16; o > 0; o >>= 1) s1 += __shfl_xor_sync(0xffffffffu, s1, o);
    float mean = s1 * (1.f / 64.f);
    float dx = vx - mean, dy = vy - mean;
    float s2 = dx * dx + dy * dy;
#pragma unroll
    for (int o = 16; o > 0; o >>= 1) s2 += __shfl_xor_sync(0xffffffffu, s2, o);
    float r = rsqrtf(s2 * (1.f / 64.f) + 1e-5f);
    float2 gg = *(const float2*)&ln_g[layer * 64 + 2 * lane];
    float2 bb = *(const float2*)&ln_b[layer * 64 + 2 * lane];
    float2 outv;
    outv.x = fmaf(dx * r, gg.x, bb.x);
    outv.y = fmaf(dy * r, gg.y, bb.y);
    *(float2*)&g_h[node * 64 + 2 * lane] = outv;
}

// ---------------- persistent output projection ----------------
__global__ void __launch_bounds__(GEMM_THREADS)
out_kernel(int n, const float* __restrict__ w,
           const float* __restrict__ b, float* __restrict__ out) {
    __shared__ float sW[64 * 64];
    __shared__ float sB[64];
    __shared__ __align__(16) float4 sH4[4][64];
    int tid = threadIdx.x;
    for (int i = tid; i < 64 * 64; i += GEMM_THREADS) sW[i] = w[i];
    if (tid < 64) sB[tid] = b[tid];
    int g = tid >> 6, j = tid & 63;
    int ntiles = (n + 15) >> 4;
    for (int tile = blockIdx.x; tile < ntiles; tile += gridDim.x) {
        int base = tile << 4;
        __syncthreads();
        for (int idx = tid; idx < 1024; idx += GEMM_THREADS) {
            int nl = idx >> 6, k = idx & 63;
            int node = base + nl;
            float v = (node < n) ? g_h[node * 64 + k] : 0.f;
            ((float*)&sH4[nl >> 2][k])[nl & 3] = v;
        }
        __syncthreads();
        unsigned long long acc01 = 0ull, acc23 = 0ull;
#pragma unroll 8
        for (int k = 0; k < 64; k++) {
            float wv = sW[k * 64 + j];
            unsigned long long w2p = pack2(wv, wv);
            float4 hv = sH4[g][k];
            acc01 = fma2(pack2(hv.x, hv.y), w2p, acc01);
            acc23 = fma2(pack2(hv.z, hv.w), w2p, acc23);
        }
        float a0, a1, a2, a3;
        unpack2(acc01, a0, a1); unpack2(acc23, a2, a3);
        float bb = sB[j];
        int n0 = base + g * 4;
        if (n0 + 0 < n) out[(n0 + 0) * 64 + j] = a0 + bb;
        if (n0 + 1 < n) out[(n0 + 1) * 64 + j] = a1 + bb;
        if (n0 + 2 < n) out[(n0 + 2) * 64 + j] = a2 + bb;
        if (n0 + 3 < n) out[(n0 + 3) * 64 + j] = a3 + bb;
    }
}

// ---------------- launcher ----------------
extern "C" void kernel_launch(void* const* d_in, const int* in_sizes, int n_in,
                              void* d_out, int out_size) {
    const float* x       = (const float*)d_in[0];
    const int* ei        = (const int*)d_in[1];     // int64 in reference -> int32 in harness
    const float* ea      = (const float*)d_in[2];
    const float* w_ne1   = (const float*)d_in[3];
    const float* b_ne1   = (const float*)d_in[4];
    const float* w_ne2   = (const float*)d_in[5];
    const float* b_ne2   = (const float*)d_in[6];
    const float* w_ee    = (const float*)d_in[7];
    const float* b_ee    = (const float*)d_in[8];
    const float* w_gat   = (const float*)d_in[9];
    const float* w_eg    = (const float*)d_in[10];
    const float* att_src = (const float*)d_in[11];
    const float* att_dst = (const float*)d_in[12];
    const float* att_edge= (const float*)d_in[13];
    const float* b_gat   = (const float*)d_in[14];
    const float* ln_g    = (const float*)d_in[15];
    const float* ln_b    = (const float*)d_in[16];
    const float* w_out   = (const float*)d_in[17];
    const float* b_out   = (const float*)d_in[18];

    int n = in_sizes[0] / 6;       // nodes
    int e = in_sizes[1] / 2;       // edges

    // CSR build (per call; graph-capturable, deterministic output)
    zero_deg_kernel<<<(n + 255) / 256, 256>>>(n);
    count_deg_kernel<<<(e / 4 + 255) / 256, 256>>>(ei, e);
    scan_kernel<<<1, 1024>>>(n);
    scatter_kernel<<<(e / 4 + 255) / 256, 256>>>(ei, ea, e);

    edge_coef_kernel<<<1, 64>>>(w_ee, b_ee, w_eg, att_edge);
    encoder_kernel<<<GEMM_GRID, GEMM_THREADS>>>(n, x, w_ne1, b_ne1, w_ne2, b_ne2);

    for (int l = 0; l < NLAYER; l++) {
        transform_kernel<<<GEMM_GRID, GEMM_THREADS>>>(n, l, w_gat, att_src, att_dst);
        gat_fused_kernel<<<(n + 3) / 4, 128>>>(n, l, b_gat, ln_g, ln_b);
    }

    out_kernel<<<GEMM_GRID, GEMM_THREADS>>>(n, w_out, b_out, (float*)d_out);
}